// round 2
// baseline (speedup 1.0000x reference)
#include <cuda_runtime.h>
#include <cuda_bf16.h>

#define ROWS 32768
#define H 1024
#define THREADS 256
#define WARPS_PER_BLOCK (THREADS / 32)
#define GRID 296   // 2 blocks per SM on 148 SMs

__global__ void zero_out_kernel(float* __restrict__ out) {
    int i = blockIdx.x * blockDim.x + threadIdx.x;
    if (i < H) out[i] = 0.0f;
}

__global__ __launch_bounds__(THREADS)
void bahdanau_cos_attn_kernel(const float* __restrict__ query,
                              const float* __restrict__ keys,
                              float* __restrict__ out) {
    __shared__ float acc_s[H];

    const int tid  = threadIdx.x;
    const int lane = tid & 31;
    const int warp = tid >> 5;

    // Zero the block-level accumulator
    for (int i = tid; i < H; i += THREADS) acc_s[i] = 0.0f;
    __syncthreads();

    // Load q into registers: lane owns elements h = (j*32 + lane)*4 .. +3
    const float4* q4 = reinterpret_cast<const float4*>(query);
    float4 q[8];
#pragma unroll
    for (int j = 0; j < 8; j++) q[j] = q4[j * 32 + lane];

    // q norm (identical in every warp, deterministic)
    float qn2 = 0.0f;
#pragma unroll
    for (int j = 0; j < 8; j++)
        qn2 += q[j].x * q[j].x + q[j].y * q[j].y + q[j].z * q[j].z + q[j].w * q[j].w;
#pragma unroll
    for (int o = 16; o > 0; o >>= 1) qn2 += __shfl_xor_sync(0xffffffffu, qn2, o);
    const float inv_qn = rsqrtf(qn2);

    // Persistent per-lane accumulator for the weighted sum
    float4 acc[8];
#pragma unroll
    for (int j = 0; j < 8; j++) acc[j] = make_float4(0.f, 0.f, 0.f, 0.f);

    const int gwarp  = blockIdx.x * WARPS_PER_BLOCK + warp;
    const int nwarps = gridDim.x * WARPS_PER_BLOCK;
    const float4* k4 = reinterpret_cast<const float4*>(keys);

    for (int row = gwarp; row < ROWS; row += nwarps) {
        const float4* kr = k4 + (size_t)row * (H / 4) + lane;

        // Batch all 8 LDG.128 up front for MLP
        float4 kv[8];
#pragma unroll
        for (int j = 0; j < 8; j++) kv[j] = kr[j * 32];

        float dot = 0.0f, n2 = 0.0f;
#pragma unroll
        for (int j = 0; j < 8; j++) {
            dot += kv[j].x * q[j].x + kv[j].y * q[j].y + kv[j].z * q[j].z + kv[j].w * q[j].w;
            n2  += kv[j].x * kv[j].x + kv[j].y * kv[j].y + kv[j].z * kv[j].z + kv[j].w * kv[j].w;
        }
#pragma unroll
        for (int o = 16; o > 0; o >>= 1) {
            dot += __shfl_xor_sync(0xffffffffu, dot, o);
            n2  += __shfl_xor_sync(0xffffffffu, n2, o);
        }

        const float c = dot * inv_qn * rsqrtf(n2);   // cosine score
#pragma unroll
        for (int j = 0; j < 8; j++) {
            acc[j].x += c * kv[j].x;
            acc[j].y += c * kv[j].y;
            acc[j].z += c * kv[j].z;
            acc[j].w += c * kv[j].w;
        }
    }

    // Warp accumulators -> block accumulator (spread-address smem atomics)
#pragma unroll
    for (int j = 0; j < 8; j++) {
        const int h = (j * 32 + lane) * 4;
        atomicAdd(&acc_s[h + 0], acc[j].x);
        atomicAdd(&acc_s[h + 1], acc[j].y);
        atomicAdd(&acc_s[h + 2], acc[j].z);
        atomicAdd(&acc_s[h + 3], acc[j].w);
    }
    __syncthreads();

    // Block accumulator -> global (296 adds per address at L2, cheap)
    for (int i = tid; i < H; i += THREADS) atomicAdd(&out[i], acc_s[i]);
}

extern "C" void kernel_launch(void* const* d_in, const int* in_sizes, int n_in,
                              void* d_out, int out_size) {
    const float* query = (const float*)d_in[0];   // [1, 1024]
    const float* keys  = (const float*)d_in[1];   // [32768, 1024]
    float* out = (float*)d_out;                   // [1, 1024]

    zero_out_kernel<<<(H + 255) / 256, 256>>>(out);
    bahdanau_cos_attn_kernel<<<GRID, THREADS>>>(query, keys, out);
}